// round 4
// baseline (speedup 1.0000x reference)
#include <cuda_runtime.h>

// HWnet: B scalar queries vs sorted anchor grid (linspace), 9-point softmax
// window gather over vector_table[T=2048, D=64].
//
// Phase A: 128 threads compute 128 queries' scalar parts (nearest index via
//          uniform-grid guess + exact local argmin refine, softmax weights)
//          -> shared memory, computed once per query.
// Phase B: 2048 (query, float4-chunk) tasks swept by 256 threads; chunk id is
//          per-thread invariant, weights fetched as float4 LDS, x2 unroll with
//          split accumulators for ~18 outstanding gathers per thread.

#define T_T   2048
#define D_D   64
#define E_E   4
#define W_W   9
#define NQ    128      // queries per block
#define NTHR  256

__global__ __launch_bounds__(NTHR, 4) void hwnet_kernel(
    const float* __restrict__ x,
    const float* __restrict__ ev,
    const float* __restrict__ tc,
    const float* __restrict__ vec,
    const int*   __restrict__ idx_tab,
    float*       __restrict__ out,
    int nq)
{
    // Per query: [0..8] normalized weights, [9] clamped base index (int bits).
    // Row stride 12 floats -> float4-aligned weight loads.
    __shared__ float sw[NQ][12];
    __shared__ int   sidx[W_W];

    int tid = threadIdx.x;
    if (tid < W_W) sidx[tid] = idx_tab[tid];

    int q0 = blockIdx.x * NQ;

    // ---------------- Phase A: per-query scalars -------------------------
    if (tid < NQ) {
        int q = q0 + tid;
        if (q < nq) {
            float xv = __ldg(&x[q]);

            // Uniform-grid guess (ev is linspace), exact +-2 argmin refine
            // with strict-< first-index tie-break (matches reference argmin).
            float e0 = __ldg(&ev[0]);
            float eN = __ldg(&ev[T_T - 1]);
            float inv_step = (float)(T_T - 1) / (eN - e0);
            int g = __float2int_rn((xv - e0) * inv_step);
            g = min(max(g, 0), T_T - 1);

            int lo = max(g - 2, 0), hi = min(g + 2, T_T - 1);
            int nidx = lo;
            float bd = 3.402823466e+38f;
            for (int j = lo; j <= hi; ++j) {
                float d = xv - __ldg(&ev[j]);
                d = d * d;
                if (d < bd) { bd = d; nidx = j; }
            }

            // takecare uses UNCLAMPED nearest idx; window uses clamped.
            float take = __ldg(&tc[nidx]);
            int idx_c = min(max(nidx, E_E), T_T - 1 - E_E);

            float lg[W_W];
            float m = -3.402823466e+38f;
            #pragma unroll
            for (int j = 0; j < W_W; ++j) {
                int w = idx_c + __ldg(&idx_tab[j]);
                float d = xv - __ldg(&ev[w]);
                float l = -(d * d) * take;
                lg[j] = l;
                m = fmaxf(m, l);
            }
            float ssum = 0.0f;
            #pragma unroll
            for (int j = 0; j < W_W; ++j) {
                float e = __expf(lg[j] - m);
                lg[j] = e;
                ssum += e;
            }
            float inv = __frcp_rn(ssum);
            #pragma unroll
            for (int j = 0; j < W_W; ++j)
                sw[tid][j] = lg[j] * inv;
            sw[tid][9] = __int_as_float(idx_c);
        }
    }
    __syncthreads();

    // Window offsets into registers (uniform across block).
    int s[W_W];
    #pragma unroll
    for (int j = 0; j < W_W; ++j) s[j] = sidx[j];

    // ---------------- Phase B: gathers -----------------------------------
    const int c = tid & 15;            // float4 chunk of D (thread-invariant)
    const int ql0 = tid >> 4;          // base local query

    if (q0 + NQ <= nq) {
        // Full block: compile-time trip count, x2 unroll.
        #pragma unroll 2
        for (int r = 0; r < (NQ * 16) / NTHR; ++r) {
            int ql = r * (NTHR / 16) + ql0;

            float4 w03 = *reinterpret_cast<const float4*>(&sw[ql][0]);
            float4 w47 = *reinterpret_cast<const float4*>(&sw[ql][4]);
            float  w8  = sw[ql][8];
            int    base = __float_as_int(sw[ql][9]);

            const float4* vp =
                reinterpret_cast<const float4*>(vec + (size_t)base * D_D) + c;

            float4 v0 = __ldg(vp + s[0] * (D_D / 4));
            float4 v1 = __ldg(vp + s[1] * (D_D / 4));
            float4 v2 = __ldg(vp + s[2] * (D_D / 4));
            float4 v3 = __ldg(vp + s[3] * (D_D / 4));
            float4 v4 = __ldg(vp + s[4] * (D_D / 4));
            float4 v5 = __ldg(vp + s[5] * (D_D / 4));
            float4 v6 = __ldg(vp + s[6] * (D_D / 4));
            float4 v7 = __ldg(vp + s[7] * (D_D / 4));
            float4 v8 = __ldg(vp + s[8] * (D_D / 4));

            // Split accumulators (even/odd) to shorten dependency chains.
            float4 a, b;
            a.x = w03.x * v0.x; a.y = w03.x * v0.y;
            a.z = w03.x * v0.z; a.w = w03.x * v0.w;
            b.x = w03.y * v1.x; b.y = w03.y * v1.y;
            b.z = w03.y * v1.z; b.w = w03.y * v1.w;

            a.x = fmaf(w03.z, v2.x, a.x); a.y = fmaf(w03.z, v2.y, a.y);
            a.z = fmaf(w03.z, v2.z, a.z); a.w = fmaf(w03.z, v2.w, a.w);
            b.x = fmaf(w03.w, v3.x, b.x); b.y = fmaf(w03.w, v3.y, b.y);
            b.z = fmaf(w03.w, v3.z, b.z); b.w = fmaf(w03.w, v3.w, b.w);

            a.x = fmaf(w47.x, v4.x, a.x); a.y = fmaf(w47.x, v4.y, a.y);
            a.z = fmaf(w47.x, v4.z, a.z); a.w = fmaf(w47.x, v4.w, a.w);
            b.x = fmaf(w47.y, v5.x, b.x); b.y = fmaf(w47.y, v5.y, b.y);
            b.z = fmaf(w47.y, v5.z, b.z); b.w = fmaf(w47.y, v5.w, b.w);

            a.x = fmaf(w47.z, v6.x, a.x); a.y = fmaf(w47.z, v6.y, a.y);
            a.z = fmaf(w47.z, v6.z, a.z); a.w = fmaf(w47.z, v6.w, a.w);
            b.x = fmaf(w47.w, v7.x, b.x); b.y = fmaf(w47.w, v7.y, b.y);
            b.z = fmaf(w47.w, v7.z, b.z); b.w = fmaf(w47.w, v7.w, b.w);

            a.x = fmaf(w8, v8.x, a.x); a.y = fmaf(w8, v8.y, a.y);
            a.z = fmaf(w8, v8.z, a.z); a.w = fmaf(w8, v8.w, a.w);

            float4 acc = make_float4(a.x + b.x, a.y + b.y,
                                     a.z + b.z, a.w + b.w);
            reinterpret_cast<float4*>(out)[(size_t)(q0 + ql) * 16 + c] = acc;
        }
    } else {
        // Partial tail block.
        int nq_blk = nq - q0;
        for (int r = 0; r < (NQ * 16) / NTHR; ++r) {
            int ql = r * (NTHR / 16) + ql0;
            if (ql >= nq_blk) break;
            int base = __float_as_int(sw[ql][9]);
            const float4* vp =
                reinterpret_cast<const float4*>(vec + (size_t)base * D_D) + c;
            float4 acc = make_float4(0.f, 0.f, 0.f, 0.f);
            #pragma unroll
            for (int j = 0; j < W_W; ++j) {
                float wgt = sw[ql][j];
                float4 v = __ldg(vp + s[j] * (D_D / 4));
                acc.x = fmaf(wgt, v.x, acc.x);
                acc.y = fmaf(wgt, v.y, acc.y);
                acc.z = fmaf(wgt, v.z, acc.z);
                acc.w = fmaf(wgt, v.w, acc.w);
            }
            reinterpret_cast<float4*>(out)[(size_t)(q0 + ql) * 16 + c] = acc;
        }
    }
}

extern "C" void kernel_launch(void* const* d_in, const int* in_sizes, int n_in,
                              void* d_out, int out_size)
{
    const float* x    = (const float*)d_in[0];
    const float* ev   = (const float*)d_in[1];
    const float* tc   = (const float*)d_in[2];
    const float* vec  = (const float*)d_in[3];
    const int*   itab = (const int*)d_in[4];
    float* out = (float*)d_out;

    int nq = in_sizes[0];
    int grid = (nq + NQ - 1) / NQ;
    hwnet_kernel<<<grid, NTHR>>>(x, ev, tc, vec, itab, out, nq);
}

// round 5
// speedup vs baseline: 1.6948x; 1.6948x over previous
#include <cuda_runtime.h>

// HWnet: B scalar queries vs sorted anchor grid (linspace), 9-point softmax
// window gather over vector_table[T=2048, D=64].
//
// Two-kernel split (both fully parallel, no intra-block phase imbalance):
//  K1: one thread per query -> nearest idx + 9 normalized weights -> scratch.
//  K2: one thread per (query, float4 chunk): 3 broadcast weight loads +
//      9 contiguous-row float4 gathers + FMA + coalesced store.
//      Max parallelism (2M threads) to fill 64-warp SMs; low regs.

#define B_Q   131072
#define T_T   2048
#define D_D   64
#define E_E   4
#define W_W   9

// Scratch: per query 3 float4 = {w0..w3, w4..w7, w8, base(intbits), pad, pad}
__device__ float4 g_wscratch[(size_t)B_Q * 3];

__global__ __launch_bounds__(256) void hwnet_weights_kernel(
    const float* __restrict__ x,
    const float* __restrict__ ev,
    const float* __restrict__ tc,
    const int*   __restrict__ idx_tab,
    int nq)
{
    int q = blockIdx.x * blockDim.x + threadIdx.x;
    if (q >= nq) return;

    float xv = __ldg(&x[q]);

    // Uniform-grid guess (ev is linspace), exact +-2 argmin refine with
    // strict-< first-index tie-break (matches reference argmin).
    float e0 = __ldg(&ev[0]);
    float eN = __ldg(&ev[T_T - 1]);
    float inv_step = (float)(T_T - 1) / (eN - e0);
    int g = __float2int_rn((xv - e0) * inv_step);
    g = min(max(g, 0), T_T - 1);

    int lo = max(g - 2, 0), hi = min(g + 2, T_T - 1);
    int nidx = lo;
    float bd = 3.402823466e+38f;
    for (int j = lo; j <= hi; ++j) {
        float d = xv - __ldg(&ev[j]);
        d = d * d;
        if (d < bd) { bd = d; nidx = j; }
    }

    // takecare uses UNCLAMPED nearest idx; window uses clamped.
    float take = __ldg(&tc[nidx]);
    int idx_c = min(max(nidx, E_E), T_T - 1 - E_E);

    float lg[W_W];
    float m = -3.402823466e+38f;
    #pragma unroll
    for (int j = 0; j < W_W; ++j) {
        int w = idx_c + __ldg(&idx_tab[j]);
        float d = xv - __ldg(&ev[w]);
        float l = -(d * d) * take;
        lg[j] = l;
        m = fmaxf(m, l);
    }
    float ssum = 0.0f;
    #pragma unroll
    for (int j = 0; j < W_W; ++j) {
        float e = __expf(lg[j] - m);
        lg[j] = e;
        ssum += e;
    }
    float inv = __frcp_rn(ssum);

    float4 a = make_float4(lg[0] * inv, lg[1] * inv, lg[2] * inv, lg[3] * inv);
    float4 b = make_float4(lg[4] * inv, lg[5] * inv, lg[6] * inv, lg[7] * inv);
    float4 cc = make_float4(lg[8] * inv, __int_as_float(idx_c), 0.f, 0.f);
    g_wscratch[(size_t)q * 3 + 0] = a;
    g_wscratch[(size_t)q * 3 + 1] = b;
    g_wscratch[(size_t)q * 3 + 2] = cc;
}

__global__ __launch_bounds__(256) void hwnet_gather_kernel(
    const float* __restrict__ vec,
    float*       __restrict__ out,
    int nq)
{
    int tid = blockIdx.x * blockDim.x + threadIdx.x;
    int q = tid >> 4;          // query
    int c = tid & 15;          // float4 chunk of D
    if (q >= nq) return;

    // Broadcast weight loads (all 16 lanes of a query hit the same lines).
    float4 w03 = __ldg(&g_wscratch[(size_t)q * 3 + 0]);
    float4 w47 = __ldg(&g_wscratch[(size_t)q * 3 + 1]);
    float4 w8b = __ldg(&g_wscratch[(size_t)q * 3 + 2]);
    int base = __float_as_int(w8b.y);

    // Window rows are contiguous: rows [base-4, base+4].
    const float4* vp =
        reinterpret_cast<const float4*>(vec + (size_t)(base - E_E) * D_D) + c;

    float wj[W_W] = {w03.x, w03.y, w03.z, w03.w,
                     w47.x, w47.y, w47.z, w47.w, w8b.x};

    float4 acc = make_float4(0.f, 0.f, 0.f, 0.f);
    #pragma unroll
    for (int j = 0; j < W_W; ++j) {
        float4 v = __ldg(vp + j * (D_D / 4));
        acc.x = fmaf(wj[j], v.x, acc.x);
        acc.y = fmaf(wj[j], v.y, acc.y);
        acc.z = fmaf(wj[j], v.z, acc.z);
        acc.w = fmaf(wj[j], v.w, acc.w);
    }

    reinterpret_cast<float4*>(out)[(size_t)q * 16 + c] = acc;
}

extern "C" void kernel_launch(void* const* d_in, const int* in_sizes, int n_in,
                              void* d_out, int out_size)
{
    const float* x    = (const float*)d_in[0];
    const float* ev   = (const float*)d_in[1];
    const float* tc   = (const float*)d_in[2];
    const float* vec  = (const float*)d_in[3];
    const int*   itab = (const int*)d_in[4];
    float* out = (float*)d_out;

    int nq = in_sizes[0];

    int grid1 = (nq + 255) / 256;
    hwnet_weights_kernel<<<grid1, 256>>>(x, ev, tc, itab, nq);

    int grid2 = (nq * 16 + 255) / 256;
    hwnet_gather_kernel<<<grid2, 256>>>(vec, out, nq);
}